// round 1
// baseline (speedup 1.0000x reference)
#include <cuda_runtime.h>
#include <cstdint>
#include <cmath>

typedef unsigned long long ull;

#define DM 768
#define NQ 256
#define NM 512

// ---------------- scratch (__device__ globals; no allocation allowed) -------
__device__ float g_q  [NQ*DM];
__device__ float g_ip [NM*DM];
__device__ float g_tp [NM*DM];
__device__ float g_qh [NQ*DM];
__device__ float g_kd [NM*DM];
__device__ float g_vd [NM*DM];
__device__ float g_vt [NM*DM];
__device__ float g_W01[DM*256];
__device__ float g_b01[256];
__device__ float g_Ah [NM*8*256];   // [m][h][256]
__device__ float g_Bm [NM*256];     // [m][256]
__device__ float g_w  [NQ*NM*8];    // [n][m][h]

// ---------------- generic multi-GEMM: C = scale*( (A - A2?) @ W + bias ) ----
struct GDesc {
    const float* A;
    const float* A2;     // optional: compute (A - A2)
    const float* W;      // K x N row-major (ldw)
    const float* bias;   // optional, length N (at n0 offset)
    float*       C;
    int M, N, K, lda, ldw, ldc;
    float scale;
};
struct GParams { GDesc d[9]; };

__global__ __launch_bounds__(256) void sgemm_multi(GParams p) {
    GDesc d = p.d[blockIdx.z];
    const int m0 = blockIdx.y * 64, n0 = blockIdx.x * 64;
    if (m0 >= d.M || n0 >= d.N) return;

    __shared__ __align__(16) float As[16][68];
    __shared__ __align__(16) float Ws[16][68];

    const int tid = threadIdx.x;
    const int tx = tid & 15, ty = tid >> 4;
    const int arow = tid >> 2, ac4 = tid & 3;    // A tile: 64 rows x 16 cols
    const int wrow = tid >> 4, wc4 = tid & 15;   // W tile: 16 rows x 64 cols

    const float* Ap  = d.A + (size_t)(m0 + arow) * d.lda + ac4 * 4;
    const float* A2p = d.A2 ? d.A2 + (size_t)(m0 + arow) * d.lda + ac4 * 4 : 0;
    const float* Wp  = d.W + (size_t)wrow * d.ldw + n0 + wc4 * 4;

    float acc[4][4];
#pragma unroll
    for (int i = 0; i < 4; i++)
#pragma unroll
        for (int j = 0; j < 4; j++) acc[i][j] = 0.f;

    for (int k0 = 0; k0 < d.K; k0 += 16) {
        float4 av = *(const float4*)(Ap + k0);
        if (A2p) {
            float4 a2 = *(const float4*)(A2p + k0);
            av.x -= a2.x; av.y -= a2.y; av.z -= a2.z; av.w -= a2.w;
        }
        float4 wv = *(const float4*)(Wp + (size_t)k0 * d.ldw);
        __syncthreads();
        As[ac4*4+0][arow] = av.x;
        As[ac4*4+1][arow] = av.y;
        As[ac4*4+2][arow] = av.z;
        As[ac4*4+3][arow] = av.w;
        *(float4*)&Ws[wrow][wc4*4] = wv;
        __syncthreads();
#pragma unroll
        for (int k = 0; k < 16; k++) {
            float4 a = *(const float4*)&As[k][ty*4];
            float4 b = *(const float4*)&Ws[k][tx*4];
            float ar[4] = {a.x, a.y, a.z, a.w};
            float br[4] = {b.x, b.y, b.z, b.w};
#pragma unroll
            for (int i = 0; i < 4; i++)
#pragma unroll
                for (int j = 0; j < 4; j++)
                    acc[i][j] = fmaf(ar[i], br[j], acc[i][j]);
        }
    }

    float4 b4 = make_float4(0.f, 0.f, 0.f, 0.f);
    if (d.bias) b4 = *(const float4*)(d.bias + n0 + tx*4);
#pragma unroll
    for (int i = 0; i < 4; i++) {
        int row = m0 + ty*4 + i;
        float4 o;
        o.x = d.scale * (acc[i][0] + b4.x);
        o.y = d.scale * (acc[i][1] + b4.y);
        o.z = d.scale * (acc[i][2] + b4.z);
        o.w = d.scale * (acc[i][3] + b4.w);
        *(float4*)(d.C + (size_t)row * d.ldc + n0 + tx*4) = o;
    }
}

// ---------------- b01 = bo @ W1 + b1 (256 outputs) -------------------------
__global__ void b01_kernel(const float* __restrict__ bo, const float* __restrict__ W1,
                           const float* __restrict__ b1, float* __restrict__ b01) {
    int j = threadIdx.x;   // 256
    float s = b1[j];
#pragma unroll 8
    for (int k = 0; k < DM; k++)
        s = fmaf(bo[k], W1[(size_t)k*256 + j], s);
    b01[j] = s;
}

// ---------------- logits: w[n,m,h] = sigmoid( qh[n,h,:] . kd[m,h,:] ) ------
__global__ __launch_bounds__(256) void logits_kernel(const float* __restrict__ qh,
                                                     const float* __restrict__ kd,
                                                     float* __restrict__ wbuf) {
    const int h  = blockIdx.z;
    const int m0 = blockIdx.x * 64, n0 = blockIdx.y * 64;
    __shared__ __align__(16) float Qs[16][68];
    __shared__ __align__(16) float Ks[16][68];

    const int tid = threadIdx.x;
    const int tx = tid & 15, ty = tid >> 4;
    const int lrow = tid >> 2, lc4 = tid & 3;

    const float* qp = qh + (size_t)(n0 + lrow)*DM + h*96 + lc4*4;
    const float* kp = kd + (size_t)(m0 + lrow)*DM + h*96 + lc4*4;

    float acc[4][4];
#pragma unroll
    for (int i = 0; i < 4; i++)
#pragma unroll
        for (int j = 0; j < 4; j++) acc[i][j] = 0.f;

    for (int k0 = 0; k0 < 96; k0 += 16) {
        float4 qv = *(const float4*)(qp + k0);
        float4 kv = *(const float4*)(kp + k0);
        __syncthreads();
        Qs[lc4*4+0][lrow] = qv.x;
        Qs[lc4*4+1][lrow] = qv.y;
        Qs[lc4*4+2][lrow] = qv.z;
        Qs[lc4*4+3][lrow] = qv.w;
        Ks[lc4*4+0][lrow] = kv.x;
        Ks[lc4*4+1][lrow] = kv.y;
        Ks[lc4*4+2][lrow] = kv.z;
        Ks[lc4*4+3][lrow] = kv.w;
        __syncthreads();
#pragma unroll
        for (int k = 0; k < 16; k++) {
            float4 a = *(const float4*)&Qs[k][ty*4];
            float4 b = *(const float4*)&Ks[k][tx*4];
            float ar[4] = {a.x, a.y, a.z, a.w};
            float br[4] = {b.x, b.y, b.z, b.w};
#pragma unroll
            for (int i = 0; i < 4; i++)
#pragma unroll
                for (int j = 0; j < 4; j++)
                    acc[i][j] = fmaf(ar[i], br[j], acc[i][j]);
        }
    }
#pragma unroll
    for (int i = 0; i < 4; i++)
#pragma unroll
        for (int j = 0; j < 4; j++) {
            int n = n0 + ty*4 + i, m = m0 + tx*4 + j;
            float wv = 1.f / (1.f + expf(-acc[i][j]));
            wbuf[((size_t)n*NM + m)*8 + h] = wv;
        }
}

// ---------------- fused tail: h=relu(B+Σw·A); h2=relu(h@W2+b2); tanh -------
__global__ __launch_bounds__(256, 2) void fuse_kernel(
    const float* __restrict__ Abuf, const float* __restrict__ Bbuf,
    const float* __restrict__ wbuf, const float* __restrict__ W2,
    const float* __restrict__ b2, const float* __restrict__ W3,
    const float* __restrict__ b3, float* __restrict__ out) {

    __shared__ __align__(16) float A_s[8*256];
    __shared__ __align__(16) float B_s[256];
    __shared__ __align__(16) float w2s[64*64];   // chunk of 64 j-rows of W2
    __shared__ float b2s[64], W3s[64];
    __shared__ float b3s;

    const int m = blockIdx.x, tid = threadIdx.x;

    // stage A[m] (8x256) and B[m] (256)
    {
        const float4* Ag = (const float4*)(Abuf + (size_t)m*2048);
        float4* A4 = (float4*)A_s;
        A4[tid]       = Ag[tid];
        A4[tid + 256] = Ag[tid + 256];
        B_s[tid] = Bbuf[(size_t)m*256 + tid];
        if (tid < 64) { b2s[tid] = b2[tid]; W3s[tid] = W3[tid]; }
        if (tid == 0) b3s = b3[0];
    }

    const int n = tid;
    const float4* wp = (const float4*)(wbuf + ((size_t)n*NM + m)*8);
    float4 wA = wp[0], wB = wp[1];
    float wr[8] = {wA.x, wA.y, wA.z, wA.w, wB.x, wB.y, wB.z, wB.w};

    ull acc[32];
#pragma unroll
    for (int t = 0; t < 32; t++) acc[t] = 0ULL;

    for (int c = 0; c < 4; c++) {
        __syncthreads();
        {
            const float4* w2g = (const float4*)(W2 + c*4096);
            float4* w2s4 = (float4*)w2s;
#pragma unroll
            for (int r = 0; r < 4; r++) w2s4[tid + r*256] = w2g[tid + r*256];
        }
        __syncthreads();

        for (int jj = 0; jj < 64; jj += 4) {
            const int j = c*64 + jj;
            float4 hb = *(const float4*)&B_s[j];
            float hv[4] = {hb.x, hb.y, hb.z, hb.w};
#pragma unroll
            for (int h = 0; h < 8; h++) {
                float4 a = *(const float4*)&A_s[h*256 + j];
                hv[0] = fmaf(wr[h], a.x, hv[0]);
                hv[1] = fmaf(wr[h], a.y, hv[1]);
                hv[2] = fmaf(wr[h], a.z, hv[2]);
                hv[3] = fmaf(wr[h], a.w, hv[3]);
            }
#pragma unroll
            for (int u = 0; u < 4; u++) {
                float hj = fmaxf(hv[u], 0.f);
                ull hh;
                asm("mov.b64 %0, {%1, %1};" : "=l"(hh) : "f"(hj));
                const ulonglong2* row = (const ulonglong2*)(w2s + (jj + u)*64);
#pragma unroll
                for (int t = 0; t < 16; t++) {
                    ulonglong2 pv = row[t];
                    asm("fma.rn.f32x2 %0, %1, %2, %0;" : "+l"(acc[2*t+0]) : "l"(hh), "l"(pv.x));
                    asm("fma.rn.f32x2 %0, %1, %2, %0;" : "+l"(acc[2*t+1]) : "l"(hh), "l"(pv.y));
                }
            }
        }
    }

    float s = b3s;
#pragma unroll
    for (int t = 0; t < 32; t++) {
        float lo, hi;
        asm("mov.b64 {%0, %1}, %2;" : "=f"(lo), "=f"(hi) : "l"(acc[t]));
        lo = fmaxf(lo + b2s[2*t+0], 0.f);
        hi = fmaxf(hi + b2s[2*t+1], 0.f);
        s = fmaf(lo, W3s[2*t+0], s);
        s = fmaf(hi, W3s[2*t+1], s);
    }
    out[(size_t)n*NM + m] = 0.5f * tanhf(s);
}

// ---------------- launch ----------------------------------------------------
extern "C" void kernel_launch(void* const* d_in, const int* in_sizes, int n_in,
                              void* d_out, int out_size) {
    const float* Q   = (const float*)d_in[0];
    const float* IMG = (const float*)d_in[1];
    const float* TGT = (const float*)d_in[2];
    const float* Wq  = (const float*)d_in[3];
    const float* bq  = (const float*)d_in[4];
    const float* Wi  = (const float*)d_in[5];
    const float* bi  = (const float*)d_in[6];
    const float* Wt  = (const float*)d_in[7];
    const float* bt  = (const float*)d_in[8];
    const float* Wiq = (const float*)d_in[9];
    const float* biq = (const float*)d_in[10];
    const float* Wik = (const float*)d_in[11];
    const float* bik = (const float*)d_in[12]; (void)bik; // cancels in k-diff
    const float* Wiv = (const float*)d_in[13];
    const float* biv = (const float*)d_in[14];
    const float* Wo  = (const float*)d_in[15];
    const float* bo  = (const float*)d_in[16];
    const float* W1  = (const float*)d_in[17];
    const float* b1  = (const float*)d_in[18];
    const float* W2  = (const float*)d_in[19];
    const float* b2  = (const float*)d_in[20];
    const float* W3  = (const float*)d_in[21];
    const float* b3  = (const float*)d_in[22];
    float* out = (float*)d_out;

    float *q, *ip, *tp, *qh, *kd, *vd, *vt, *W01, *b01, *Ah, *Bm, *wb;
    cudaGetSymbolAddress((void**)&q,   g_q);
    cudaGetSymbolAddress((void**)&ip,  g_ip);
    cudaGetSymbolAddress((void**)&tp,  g_tp);
    cudaGetSymbolAddress((void**)&qh,  g_qh);
    cudaGetSymbolAddress((void**)&kd,  g_kd);
    cudaGetSymbolAddress((void**)&vd,  g_vd);
    cudaGetSymbolAddress((void**)&vt,  g_vt);
    cudaGetSymbolAddress((void**)&W01, g_W01);
    cudaGetSymbolAddress((void**)&b01, g_b01);
    cudaGetSymbolAddress((void**)&Ah,  g_Ah);
    cudaGetSymbolAddress((void**)&Bm,  g_Bm);
    cudaGetSymbolAddress((void**)&wb,  g_w);

    const float scale = 1.0f / sqrtf(96.0f);

    // L1: stage-1 projections + W01 fold (all independent)
    GParams p1 = {};
    p1.d[0] = {Q,   0, Wq, bq, q,   256, 768, 768, 768, 768, 768, 1.f};
    p1.d[1] = {IMG, 0, Wi, bi, ip,  512, 768, 768, 768, 768, 768, 1.f};
    p1.d[2] = {TGT, 0, Wt, bt, tp,  512, 768, 768, 768, 768, 768, 1.f};
    p1.d[3] = {Wo,  0, W1, 0,  W01, 768, 256, 768, 768, 256, 256, 1.f};
    sgemm_multi<<<dim3(12, 12, 4), 256>>>(p1);

    b01_kernel<<<1, 256>>>(bo, W1, b1, b01);

    // L2: stage-2 projections (k/v bias cancels in diffs)
    GParams p2 = {};
    p2.d[0] = {q,  0,  Wiq, biq, qh, 256, 768, 768, 768, 768, 768, scale};
    p2.d[1] = {ip, tp, Wik, 0,   kd, 512, 768, 768, 768, 768, 768, 1.f};
    p2.d[2] = {ip, tp, Wiv, 0,   vd, 512, 768, 768, 768, 768, 768, 1.f};
    p2.d[3] = {tp, 0,  Wiv, biv, vt, 512, 768, 768, 768, 768, 768, 1.f};
    sgemm_multi<<<dim3(12, 8, 4), 256>>>(p2);

    // L3: per-head A[m,h,:] = vd_h @ W01_h  and  B[m] = vt @ W01 + b01
    GParams p3 = {};
    for (int h = 0; h < 8; h++)
        p3.d[h] = {vd + h*96, 0, W01 + h*96*256, 0, Ah + h*256,
                   512, 256, 96, 768, 256, 2048, 1.f};
    p3.d[8] = {vt, 0, W01, b01, Bm, 512, 256, 768, 768, 256, 256, 1.f};
    sgemm_multi<<<dim3(4, 8, 9), 256>>>(p3);

    // L4: attention weights (sigmoid of logit diff)
    logits_kernel<<<dim3(8, 4, 8), 256>>>(qh, kd, wb);

    // L5: fused weighted-combine + MLP tail
    fuse_kernel<<<NM, 256>>>(Ah, Bm, wb, W2, b2, W3, b3, out);
}